// round 3
// baseline (speedup 1.0000x reference)
#include <cuda_runtime.h>

#define BATCH 2048
#define F 64
#define H 128
#define STEPS 101       // t + input_length
#define LFRAMES 102     // total_length
#define DT 0.1f

typedef unsigned long long ull;

// ---- SMEM layout (float offsets) ----
// Weights interleaved by row pairs: Wp[i2*P2F + 2c + {0,1}] = {W[2i2][c], W[2i2+1][c]}
// P2F = 258 floats per row-pair (129 float2: odd pitch => conflict-free row-strided LDS.64)
#define P2F 258
#define OFF_W1 0                       // 32 pairs * 258 = 8256 floats
#define OFF_W2 (OFF_W1 + 32 * P2F)     // 8256
#define OFF_W3 (OFF_W2 + 64 * P2F)     // 24768
#define OFF_B1 (OFF_W3 + 64 * P2F)     // 41280
#define OFF_B2 (OFF_B1 + 128)
#define OFF_B3 (OFF_B2 + 128)
#define OFF_V  (OFF_B3 + 128)
#define OFF_BUF (OFF_V + 128)          // 41792 (16B aligned)
#define WARP_BUF 3072                  // bufA 1024 | bufB 1024 | bufD 1024
#define SMEM_FLOATS (OFF_BUF + 4 * WARP_BUF)   // 54080 floats = 216320 B

__device__ __align__(16) float g_back[(size_t)BATCH * LFRAMES * F];

// ---- packed f32x2 helpers ----
__device__ __forceinline__ void ffma2(ull& d, ull a, ull b) {
  asm("fma.rn.f32x2 %0, %1, %2, %0;" : "+l"(d) : "l"(a), "l"(b));
}
__device__ __forceinline__ ull pack2(float lo, float hi) {
  ull r; asm("mov.b64 %0, {%1, %2};" : "=l"(r) : "f"(lo), "f"(hi)); return r;
}
__device__ __forceinline__ void unpack2(ull v, float& lo, float& hi) {
  asm("mov.b64 {%0, %1}, %2;" : "=f"(lo), "=f"(hi) : "l"(v));
}
__device__ __forceinline__ float ftanh(float x) {
  float e = __expf(2.0f * x);
  float r; asm("rcp.approx.f32 %0, %1;" : "=f"(r) : "f"(e + 1.0f));
  return 1.0f - 2.0f * r;   // saturates correctly at +/-1 (e=inf -> rcp=0)
}

// Forward matvec, reduction-packed:
// acc[q][r] halves accumulate even/odd reduction rows; out = lo+hi at epilogue.
// buf: natural [8][IN] floats. Wp: interleaved row pairs.
template <int IN>
__device__ __forceinline__ void mv_fwd(const float* __restrict__ Wp,
                                       const float* __restrict__ buf,
                                       ull acc[4][8], int lane) {
  const float* wbase = Wp + 2 * lane;
#pragma unroll 2
  for (int i4 = 0; i4 < IN / 4; i4++) {
    ull a0[8], a1[8];
#pragma unroll
    for (int r = 0; r < 8; r++) {
      ulonglong2 t = *(const ulonglong2*)(buf + r * IN + 4 * i4);
      a0[r] = t.x; a1[r] = t.y;
    }
    const float* w = wbase + (2 * i4) * P2F;
#pragma unroll
    for (int q = 0; q < 4; q++) {
      ull wq = *(const ull*)(w + 64 * q);
#pragma unroll
      for (int r = 0; r < 8; r++) ffma2(acc[q][r], wq, a0[r]);
    }
#pragma unroll
    for (int q = 0; q < 4; q++) {
      ull wq = *(const ull*)(w + P2F + 64 * q);
#pragma unroll
      for (int r = 0; r < 8; r++) ffma2(acc[q][r], wq, a1[r]);
    }
  }
}

// Backward (transposed) matvec, output-packed:
// acc[qp][r] = {out_2p, out_2p+1}, p = lane + 32*qp. dbuf natural [8][128].
__device__ __forceinline__ void mv_bwd(const float* __restrict__ Wp,
                                       const float* __restrict__ dbuf,
                                       ull acc[2][8], int lane) {
  const float* w0 = Wp + (size_t)lane * P2F;
  const float* w1 = Wp + (size_t)(lane + 32) * P2F;
#pragma unroll 2
  for (int c2 = 0; c2 < 64; c2++) {
    ull d0[8], d1[8];
#pragma unroll
    for (int r = 0; r < 8; r++) {
      float2 t = *(const float2*)(dbuf + r * 128 + 2 * c2);
      d0[r] = pack2(t.x, t.x);
      d1[r] = pack2(t.y, t.y);
    }
    ull wa = *(const ull*)(w0 + 4 * c2);
    ull wb = *(const ull*)(w1 + 4 * c2);
#pragma unroll
    for (int r = 0; r < 8; r++) ffma2(acc[0][r], wa, d0[r]);
#pragma unroll
    for (int r = 0; r < 8; r++) ffma2(acc[1][r], wb, d0[r]);
    wa = *(const ull*)(w0 + 4 * c2 + 2);
    wb = *(const ull*)(w1 + 4 * c2 + 2);
#pragma unroll
    for (int r = 0; r < 8; r++) ffma2(acc[0][r], wa, d1[r]);
#pragma unroll
    for (int r = 0; r < 8; r++) ffma2(acc[1][r], wb, d1[r]);
  }
}

__global__ void __launch_bounds__(128, 1)
ham_kernel(const float* __restrict__ x,
           const float* __restrict__ W1, const float* __restrict__ b1,
           const float* __restrict__ W2, const float* __restrict__ b2,
           const float* __restrict__ W3, const float* __restrict__ b3,
           const float* __restrict__ W4, const float* __restrict__ W5,
           float* __restrict__ out) {
  extern __shared__ float sm[];
  const int tid = threadIdx.x;

  // ---- Stage weights interleaved by row pairs ----
  for (int idx = tid; idx < 32 * 128; idx += 128) {
    int i2 = idx >> 7, c = idx & 127;
    sm[OFF_W1 + i2 * P2F + 2 * c]     = W1[(2 * i2) * H + c];
    sm[OFF_W1 + i2 * P2F + 2 * c + 1] = W1[(2 * i2 + 1) * H + c];
  }
  for (int idx = tid; idx < 64 * 128; idx += 128) {
    int i2 = idx >> 7, c = idx & 127;
    sm[OFF_W2 + i2 * P2F + 2 * c]     = W2[(2 * i2) * H + c];
    sm[OFF_W2 + i2 * P2F + 2 * c + 1] = W2[(2 * i2 + 1) * H + c];
    sm[OFF_W3 + i2 * P2F + 2 * c]     = W3[(2 * i2) * H + c];
    sm[OFF_W3 + i2 * P2F + 2 * c + 1] = W3[(2 * i2 + 1) * H + c];
  }
  {  // biases + v = W4 @ W5[:,0]
    sm[OFF_B1 + tid] = b1[tid];
    sm[OFF_B2 + tid] = b2[tid];
    sm[OFF_B3 + tid] = b3[tid];
    float acc = 0.0f;
    for (int k = 0; k < H; k++) acc += W4[tid * H + k] * W5[k];
    sm[OFF_V + tid] = acc;
  }
  __syncthreads();

  const int warp = tid >> 5;
  const int lane = tid & 31;
  const int gw = blockIdx.x * 4 + warp;     // 0..511
  const bool bwd = (gw >= 256);
  const int b0 = (gw * 8) & (BATCH - 1);    // first of 8 rows

  float* bufA = sm + OFF_BUF + warp * WARP_BUF;  // h1 natural [8][128]
  float* bufB = bufA + 1024;                     // h2 natural [8][128]
  float* bufD = bufB + 1024;                     // y-staging / d natural [8][128]

  float y0[8], y1[8];
  const float sgn = bwd ? -1.0f : 1.0f;
  float* gbase = bwd ? g_back : out;
#pragma unroll
  for (int r = 0; r < 8; r++) {
    const float* xp = x + ((size_t)(b0 + r) * 2 + (bwd ? 1 : 0)) * F;
    y0[r] = xp[lane];
    y1[r] = sgn * xp[lane + 32];
  }
  const float inv101 = 1.0f / 101.0f;

  {  // frame 0 (weight = 1); backward frame k lands at index 101-k
    const int i = bwd ? (LFRAMES - 1) : 0;
#pragma unroll
    for (int r = 0; r < 8; r++) {
      float* p = gbase + ((size_t)(b0 + r) * LFRAMES + i) * F;
      p[lane] = y0[r];
      p[lane + 32] = sgn * y1[r];
    }
  }

#pragma unroll 1
  for (int k = 1; k <= STEPS; k++) {
    __syncwarp();
    // stage y into bufD ([8][64] view)
#pragma unroll
    for (int r = 0; r < 8; r++) {
      bufD[r * 64 + lane] = y0[r];
      bufD[r * 64 + 32 + lane] = y1[r];
    }
    __syncwarp();

    ull acc[4][8];
    float bq[4];

    // ---- fwd1: h1 = tanh(y@W1 + b1) ----
#pragma unroll
    for (int q = 0; q < 4; q++) bq[q] = sm[OFF_B1 + lane + 32 * q];
#pragma unroll
    for (int q = 0; q < 4; q++)
#pragma unroll
      for (int r = 0; r < 8; r++) acc[q][r] = pack2(bq[q], 0.0f);
    mv_fwd<64>(sm + OFF_W1, bufD, acc, lane);
    __syncwarp();
#pragma unroll
    for (int q = 0; q < 4; q++)
#pragma unroll
      for (int r = 0; r < 8; r++) {
        float lo, hi; unpack2(acc[q][r], lo, hi);
        bufA[r * 128 + lane + 32 * q] = ftanh(lo + hi);
      }
    __syncwarp();

    // ---- fwd2: h2 = tanh(h1@W2 + b2) ----
#pragma unroll
    for (int q = 0; q < 4; q++) bq[q] = sm[OFF_B2 + lane + 32 * q];
#pragma unroll
    for (int q = 0; q < 4; q++)
#pragma unroll
      for (int r = 0; r < 8; r++) acc[q][r] = pack2(bq[q], 0.0f);
    mv_fwd<128>(sm + OFF_W2, bufA, acc, lane);
    __syncwarp();
#pragma unroll
    for (int q = 0; q < 4; q++)
#pragma unroll
      for (int r = 0; r < 8; r++) {
        float lo, hi; unpack2(acc[q][r], lo, hi);
        bufB[r * 128 + lane + 32 * q] = ftanh(lo + hi);
      }
    __syncwarp();

    // ---- fwd3: d3 = v * (1 - tanh(h2@W3 + b3)^2) ----
#pragma unroll
    for (int q = 0; q < 4; q++) bq[q] = sm[OFF_B3 + lane + 32 * q];
#pragma unroll
    for (int q = 0; q < 4; q++)
#pragma unroll
      for (int r = 0; r < 8; r++) acc[q][r] = pack2(bq[q], 0.0f);
    mv_fwd<128>(sm + OFF_W3, bufB, acc, lane);
    __syncwarp();
#pragma unroll
    for (int q = 0; q < 4; q++) {
      float vq = sm[OFF_V + lane + 32 * q];
#pragma unroll
      for (int r = 0; r < 8; r++) {
        float lo, hi; unpack2(acc[q][r], lo, hi);
        float t = ftanh(lo + hi);
        bufD[r * 128 + lane + 32 * q] = vq * (1.0f - t * t);
      }
    }
    __syncwarp();

    ull accb[2][8];
    const ull z2 = pack2(0.0f, 0.0f);

    // ---- bwd1: d2 = (W3 @ d3) * (1 - h2^2) ----
#pragma unroll
    for (int qp = 0; qp < 2; qp++)
#pragma unroll
      for (int r = 0; r < 8; r++) accb[qp][r] = z2;
    mv_bwd(sm + OFF_W3, bufD, accb, lane);
    __syncwarp();
#pragma unroll
    for (int qp = 0; qp < 2; qp++) {
      const int p = lane + 32 * qp;
#pragma unroll
      for (int r = 0; r < 8; r++) {
        float lo, hi; unpack2(accb[qp][r], lo, hi);
        float2 h = *(const float2*)(bufB + r * 128 + 2 * p);
        float2 dv = make_float2(lo * (1.0f - h.x * h.x), hi * (1.0f - h.y * h.y));
        *(float2*)(bufD + r * 128 + 2 * p) = dv;
      }
    }
    __syncwarp();

    // ---- bwd2: d1 = (W2 @ d2) * (1 - h1^2) ----
#pragma unroll
    for (int qp = 0; qp < 2; qp++)
#pragma unroll
      for (int r = 0; r < 8; r++) accb[qp][r] = z2;
    mv_bwd(sm + OFF_W2, bufD, accb, lane);
    __syncwarp();
#pragma unroll
    for (int qp = 0; qp < 2; qp++) {
      const int p = lane + 32 * qp;
#pragma unroll
      for (int r = 0; r < 8; r++) {
        float lo, hi; unpack2(accb[qp][r], lo, hi);
        float2 h = *(const float2*)(bufA + r * 128 + 2 * p);
        float2 dv = make_float2(lo * (1.0f - h.x * h.x), hi * (1.0f - h.y * h.y));
        *(float2*)(bufD + r * 128 + 2 * p) = dv;
      }
    }
    __syncwarp();

    // ---- bwd3 (scalar): g = W1 @ d1, 64 outputs at features lane, lane+32 ----
    float g0[8], g1[8];
#pragma unroll
    for (int r = 0; r < 8; r++) { g0[r] = 0.0f; g1[r] = 0.0f; }
    {
      const float* w1a = sm + OFF_W1 + (lane >> 1) * P2F + (lane & 1);
      const float* w1b = w1a + 16 * P2F;  // row lane+32 -> pair (lane>>1)+16, same parity
#pragma unroll 2
      for (int j = 0; j < 128; j++) {
        float wva = w1a[2 * j];
        float wvb = w1b[2 * j];
#pragma unroll
        for (int r = 0; r < 8; r++) {
          float dv = bufD[r * 128 + j];
          g0[r] += wva * dv;
          g1[r] += wvb * dv;
        }
      }
    }

    // ---- update + emit weighted frame ----
    const float s = (float)(101 - k) * inv101;
    const int i = bwd ? (LFRAMES - 1 - k) : k;
#pragma unroll
    for (int r = 0; r < 8; r++) {
      y0[r] += DT * g1[r];
      y1[r] -= DT * g0[r];
      float* p = gbase + ((size_t)(b0 + r) * LFRAMES + i) * F;
      p[lane] = y0[r] * s;
      p[lane + 32] = sgn * y1[r] * s;
    }
  }
}

__global__ void combine_kernel(float4* __restrict__ out, int n4) {
  const float4* __restrict__ gb = (const float4*)g_back;
  int i = blockIdx.x * blockDim.x + threadIdx.x;
  const int stride = gridDim.x * blockDim.x;
  for (; i < n4; i += stride) {
    float4 o = out[i];
    float4 g = gb[i];
    o.x += g.x; o.y += g.y; o.z += g.z; o.w += g.w;
    out[i] = o;
  }
}

extern "C" void kernel_launch(void* const* d_in, const int* in_sizes, int n_in,
                              void* d_out, int out_size) {
  (void)in_sizes; (void)n_in; (void)out_size;
  // metadata order: t, x, W1, b1, W2, b2, W3, b3, W4, b4, W5, b5
  const float* x  = (const float*)d_in[1];
  const float* W1 = (const float*)d_in[2];
  const float* b1 = (const float*)d_in[3];
  const float* W2 = (const float*)d_in[4];
  const float* b2 = (const float*)d_in[5];
  const float* W3 = (const float*)d_in[6];
  const float* b3 = (const float*)d_in[7];
  const float* W4 = (const float*)d_in[8];
  const float* W5 = (const float*)d_in[10];
  float* out = (float*)d_out;

  cudaFuncSetAttribute(ham_kernel, cudaFuncAttributeMaxDynamicSharedMemorySize,
                       SMEM_FLOATS * (int)sizeof(float));

  ham_kernel<<<128, 128, SMEM_FLOATS * (int)sizeof(float)>>>(
      x, W1, b1, W2, b2, W3, b3, W4, W5, out);

  const int n4 = (BATCH * LFRAMES * F) / 4;
  combine_kernel<<<1024, 256>>>((float4*)out, n4);
}

// round 4
// speedup vs baseline: 1.0352x; 1.0352x over previous
#include <cuda_runtime.h>

// Problem constants (fixed by setup_inputs)
#define BATCH 2048
#define F 64
#define H 128
#define STEPS 101       // t + input_length = 100 + 1
#define LFRAMES 102     // total_length
#define DT 0.1f

#define WARPS_PER_CTA 7
#define THREADS (WARPS_PER_CTA * 32)   // 224
#define GRID 148
#define NJOBS 1024                     // warp-jobs (4 rows each)

// SMEM layout (float offsets). Pitch 129 => conflict-free for both
// row-contiguous (forward) and row-strided (transposed/backward) access.
#define P1 129
#define OFF_W1 0
#define OFF_W2 (OFF_W1 + 64 * P1)      // 8256
#define OFF_W3 (OFF_W2 + 128 * P1)     // 24768
#define OFF_B1 (OFF_W3 + 128 * P1)     // 41280
#define OFF_B2 (OFF_B1 + 128)
#define OFF_B3 (OFF_B2 + 128)
#define OFF_V  (OFF_B3 + 128)
#define OFF_BUF (OFF_V + 128)          // 41792
#define WARP_BUF 1280                  // per-warp: bufY 256 + bufA 512 + bufB 512
#define SMEM_FLOATS (OFF_BUF + WARPS_PER_CTA * WARP_BUF)  // 50752 floats = 203008 B

// Backward-trajectory scratch (device global: allocation-free)
__device__ __align__(16) float g_back[(size_t)BATCH * LFRAMES * F];

__device__ __forceinline__ float mytanh(float x) { return tanhf(x); }

// Forward matvec: acc[q][r] += sum_i buf[r][i] * W[i][lane+32q]
// buf is [4][IN] dense, W is SMEM at pitch P1.
template <int IN>
__device__ __forceinline__ void matvec_fwd(const float* __restrict__ Wsm,
                                           const float* __restrict__ buf,
                                           float acc[4][4], int lane) {
#pragma unroll 1
  for (int i = 0; i < IN; i += 4) {
    float4 a0 = *(const float4*)(buf + 0 * IN + i);
    float4 a1 = *(const float4*)(buf + 1 * IN + i);
    float4 a2 = *(const float4*)(buf + 2 * IN + i);
    float4 a3 = *(const float4*)(buf + 3 * IN + i);
    const float* wrow = Wsm + i * P1 + lane;
#pragma unroll
    for (int ii = 0; ii < 4; ii++) {
      float av0 = ((const float*)&a0)[ii];
      float av1 = ((const float*)&a1)[ii];
      float av2 = ((const float*)&a2)[ii];
      float av3 = ((const float*)&a3)[ii];
#pragma unroll
      for (int q = 0; q < 4; q++) {
        float w = wrow[ii * P1 + 32 * q];
        acc[q][0] += w * av0;
        acc[q][1] += w * av1;
        acc[q][2] += w * av2;
        acc[q][3] += w * av3;
      }
    }
  }
}

// Backward (transposed) matvec: acc[q][r] += sum_j W[lane+32q][j] * buf[r][j]
// buf is [4][128] dense.
template <int QN>
__device__ __forceinline__ void matvec_bwd(const float* __restrict__ Wsm,
                                           const float* __restrict__ buf,
                                           float acc[QN][4], int lane) {
  const float* wr[QN];
#pragma unroll
  for (int q = 0; q < QN; q++) wr[q] = Wsm + (lane + 32 * q) * P1;
#pragma unroll 1
  for (int j = 0; j < 128; j += 4) {
    float4 d0 = *(const float4*)(buf + 0 * 128 + j);
    float4 d1 = *(const float4*)(buf + 1 * 128 + j);
    float4 d2 = *(const float4*)(buf + 2 * 128 + j);
    float4 d3 = *(const float4*)(buf + 3 * 128 + j);
#pragma unroll
    for (int jj = 0; jj < 4; jj++) {
      float dv0 = ((const float*)&d0)[jj];
      float dv1 = ((const float*)&d1)[jj];
      float dv2 = ((const float*)&d2)[jj];
      float dv3 = ((const float*)&d3)[jj];
#pragma unroll
      for (int q = 0; q < QN; q++) {
        float w = wr[q][j + jj];
        acc[q][0] += w * dv0;
        acc[q][1] += w * dv1;
        acc[q][2] += w * dv2;
        acc[q][3] += w * dv3;
      }
    }
  }
}

__global__ void __launch_bounds__(THREADS, 1)
ham_kernel(const float* __restrict__ x,
           const float* __restrict__ W1, const float* __restrict__ b1,
           const float* __restrict__ W2, const float* __restrict__ b2,
           const float* __restrict__ W3, const float* __restrict__ b3,
           const float* __restrict__ W4, const float* __restrict__ W5,
           float* __restrict__ out) {
  extern __shared__ float sm[];
  const int tid = threadIdx.x;

  // ---- Stage weights into SMEM (pitch P1) ----
  for (int idx = tid; idx < 64 * H; idx += THREADS)
    sm[OFF_W1 + (idx >> 7) * P1 + (idx & 127)] = W1[idx];
  for (int idx = tid; idx < H * H; idx += THREADS)
    sm[OFF_W2 + (idx >> 7) * P1 + (idx & 127)] = W2[idx];
  for (int idx = tid; idx < H * H; idx += THREADS)
    sm[OFF_W3 + (idx >> 7) * P1 + (idx & 127)] = W3[idx];
  for (int idx = tid; idx < H; idx += THREADS) {
    sm[OFF_B1 + idx] = b1[idx];
    sm[OFF_B2 + idx] = b2[idx];
    sm[OFF_B3 + idx] = b3[idx];
  }
  if (tid < H) {  // v = W4 @ W5[:,0] (constant cotangent of h3)
    float acc = 0.0f;
    for (int k = 0; k < H; k++) acc += W4[tid * H + k] * W5[k];
    sm[OFF_V + tid] = acc;
  }
  __syncthreads();

  const int warp = tid >> 5;
  const int lane = tid & 31;
  const int gw = blockIdx.x * WARPS_PER_CTA + warp;  // 0..1035
  if (gw >= NJOBS) return;                           // 12 idle warps
  const bool bwd = (gw >= NJOBS / 2);
  const int b0 = (gw * 4) & (BATCH - 1);  // first of 4 rows

  float* bufY = sm + OFF_BUF + warp * WARP_BUF;  // [4][64]
  float* bufA = bufY + 256;                      // [4][128]
  float* bufB = bufY + 768;                      // [4][128]

  float y0[4], y1[4];        // state: f = lane, f = lane+32
  float* obase[4];
  const float sgn = bwd ? -1.0f : 1.0f;
#pragma unroll
  for (int r = 0; r < 4; r++) {
    const float* xp = x + ((size_t)(b0 + r) * 2 + (bwd ? 1 : 0)) * F;
    y0[r] = xp[lane];
    y1[r] = sgn * xp[lane + 32];  // vflip on backward init
    obase[r] = (bwd ? g_back : out) + (size_t)(b0 + r) * LFRAMES * F;
  }
  const float inv101 = 1.0f / 101.0f;

  // frame 0 (weight = 1); backward frame k lands at index LFRAMES-1-k
  {
    const int i = bwd ? (LFRAMES - 1) : 0;
#pragma unroll
    for (int r = 0; r < 4; r++) {
      float* p = obase[r] + i * F;
      p[lane] = y0[r];
      p[lane + 32] = sgn * y1[r];
    }
  }

#pragma unroll 1
  for (int k = 1; k <= STEPS; k++) {
    // stage in current state
    __syncwarp();
#pragma unroll
    for (int r = 0; r < 4; r++) {
      bufY[r * 64 + lane] = y0[r];
      bufY[r * 64 + 32 + lane] = y1[r];
    }
    __syncwarp();

    float h1v[4][4], h2v[4][4], acc[4][4];

    // ---- stage 1: h1 = tanh(y@W1 + b1) ----
#pragma unroll
    for (int q = 0; q < 4; q++) {
      float b = sm[OFF_B1 + lane + 32 * q];
#pragma unroll
      for (int r = 0; r < 4; r++) acc[q][r] = b;
    }
    matvec_fwd<64>(sm + OFF_W1, bufY, acc, lane);
#pragma unroll
    for (int q = 0; q < 4; q++)
#pragma unroll
      for (int r = 0; r < 4; r++) h1v[q][r] = mytanh(acc[q][r]);
    __syncwarp();
#pragma unroll
    for (int q = 0; q < 4; q++)
#pragma unroll
      for (int r = 0; r < 4; r++) bufA[r * 128 + lane + 32 * q] = h1v[q][r];
    __syncwarp();

    // ---- stage 2: h2 = tanh(h1@W2 + b2) ----
#pragma unroll
    for (int q = 0; q < 4; q++) {
      float b = sm[OFF_B2 + lane + 32 * q];
#pragma unroll
      for (int r = 0; r < 4; r++) acc[q][r] = b;
    }
    matvec_fwd<128>(sm + OFF_W2, bufA, acc, lane);
#pragma unroll
    for (int q = 0; q < 4; q++)
#pragma unroll
      for (int r = 0; r < 4; r++) h2v[q][r] = mytanh(acc[q][r]);
    __syncwarp();
#pragma unroll
    for (int q = 0; q < 4; q++)
#pragma unroll
      for (int r = 0; r < 4; r++) bufB[r * 128 + lane + 32 * q] = h2v[q][r];
    __syncwarp();

    // ---- stage 3: h3 = tanh(h2@W3 + b3); d3 = v * (1 - h3^2) ----
#pragma unroll
    for (int q = 0; q < 4; q++) {
      float b = sm[OFF_B3 + lane + 32 * q];
#pragma unroll
      for (int r = 0; r < 4; r++) acc[q][r] = b;
    }
    matvec_fwd<128>(sm + OFF_W3, bufB, acc, lane);
    __syncwarp();
#pragma unroll
    for (int q = 0; q < 4; q++) {
      float vq = sm[OFF_V + lane + 32 * q];
#pragma unroll
      for (int r = 0; r < 4; r++) {
        float t = mytanh(acc[q][r]);
        bufA[r * 128 + lane + 32 * q] = vq * (1.0f - t * t);  // d3
      }
    }
    __syncwarp();

    // ---- backward 1: d2 = (W3 @ d3) * (1 - h2^2) ----
#pragma unroll
    for (int q = 0; q < 4; q++)
#pragma unroll
      for (int r = 0; r < 4; r++) acc[q][r] = 0.0f;
    matvec_bwd<4>(sm + OFF_W3, bufA, acc, lane);
    __syncwarp();
#pragma unroll
    for (int q = 0; q < 4; q++)
#pragma unroll
      for (int r = 0; r < 4; r++)
        bufB[r * 128 + lane + 32 * q] =
            acc[q][r] * (1.0f - h2v[q][r] * h2v[q][r]);
    __syncwarp();

    // ---- backward 2: d1 = (W2 @ d2) * (1 - h1^2) ----
#pragma unroll
    for (int q = 0; q < 4; q++)
#pragma unroll
      for (int r = 0; r < 4; r++) acc[q][r] = 0.0f;
    matvec_bwd<4>(sm + OFF_W2, bufB, acc, lane);
    __syncwarp();
#pragma unroll
    for (int q = 0; q < 4; q++)
#pragma unroll
      for (int r = 0; r < 4; r++)
        bufA[r * 128 + lane + 32 * q] =
            acc[q][r] * (1.0f - h1v[q][r] * h1v[q][r]);
    __syncwarp();

    // ---- backward 3: g = W1 @ d1 (64 outputs: q = 0,1) ----
    float gacc[2][4];
#pragma unroll
    for (int q = 0; q < 2; q++)
#pragma unroll
      for (int r = 0; r < 4; r++) gacc[q][r] = 0.0f;
    matvec_bwd<2>(sm + OFF_W1, bufA, gacc, lane);

    // ---- symplectic-style update: dyn = [gp, -gq] ----
#pragma unroll
    for (int r = 0; r < 4; r++) {
      y0[r] += DT * gacc[1][r];  // f = lane   (< 32): +g[f+32]
      y1[r] -= DT * gacc[0][r];  // f = lane+32 (>=32): -g[f-32]
    }

    // ---- emit weighted frame ----
    const float s = (float)(101 - k) * inv101;  // w0(k) fwd == w1(L-1-k) bwd
    const int i = bwd ? (LFRAMES - 1 - k) : k;
#pragma unroll
    for (int r = 0; r < 4; r++) {
      float* p = obase[r] + i * F;
      p[lane] = y0[r] * s;
      p[lane + 32] = sgn * y1[r] * s;
    }
  }
}

__global__ void combine_kernel(float4* __restrict__ out, int n4) {
  const float4* __restrict__ gb = (const float4*)g_back;
  int i = blockIdx.x * blockDim.x + threadIdx.x;
  const int stride = gridDim.x * blockDim.x;
  for (; i < n4; i += stride) {
    float4 o = out[i];
    float4 g = gb[i];
    o.x += g.x; o.y += g.y; o.z += g.z; o.w += g.w;
    out[i] = o;
  }
}

extern "C" void kernel_launch(void* const* d_in, const int* in_sizes, int n_in,
                              void* d_out, int out_size) {
  (void)in_sizes; (void)n_in; (void)out_size;
  // metadata order: t, x, W1, b1, W2, b2, W3, b3, W4, b4, W5, b5
  const float* x  = (const float*)d_in[1];
  const float* W1 = (const float*)d_in[2];
  const float* b1 = (const float*)d_in[3];
  const float* W2 = (const float*)d_in[4];
  const float* b2 = (const float*)d_in[5];
  const float* W3 = (const float*)d_in[6];
  const float* b3 = (const float*)d_in[7];
  const float* W4 = (const float*)d_in[8];
  const float* W5 = (const float*)d_in[10];
  float* out = (float*)d_out;

  cudaFuncSetAttribute(ham_kernel, cudaFuncAttributeMaxDynamicSharedMemorySize,
                       SMEM_FLOATS * (int)sizeof(float));

  ham_kernel<<<GRID, THREADS, SMEM_FLOATS * (int)sizeof(float)>>>(
      x, W1, b1, W2, b2, W3, b3, W4, W5, out);

  const int n4 = (BATCH * LFRAMES * F) / 4;
  combine_kernel<<<1024, 256>>>((float4*)out, n4);
}